// round 4
// baseline (speedup 1.0000x reference)
#include <cuda_runtime.h>

#define N_NODES 20000
#define N_EDGES 10000
#define IN_CH   128
#define OUT_CH  64

// Scratch (device globals — no allocation in kernel_launch).
__device__ float g_xw[N_NODES * OUT_CH];   // x @ theta           [N, 64]
__device__ float g_ef[N_EDGES * OUT_CH];   // edge features       [E, 64]

// ---------------------------------------------------------------------------
// Kernel 1: g_xw = x @ theta.   x:[N,128], theta:[128,64]
// Block: 128 threads, 32 output rows x 64 cols. Microtile 2x8 per thread.
// ---------------------------------------------------------------------------
__global__ __launch_bounds__(128) void k_xw(const float* __restrict__ x,
                                            const float* __restrict__ theta) {
    __shared__ float a_s[32][33];   // x^T tile: [k][n], padded
    __shared__ float b_s[32][64];   // theta tile: [k][c]
    const int tid = threadIdx.x;
    const int rg  = tid >> 3;       // 0..15 -> 2 rows each
    const int cg  = tid & 7;        // 0..7  -> 8 cols each
    const int n0  = blockIdx.x * 32;

    float acc[2][8];
#pragma unroll
    for (int i = 0; i < 2; i++)
#pragma unroll
        for (int j = 0; j < 8; j++) acc[i][j] = 0.f;

    for (int k0 = 0; k0 < IN_CH; k0 += 32) {
        // A: x[n0+i][k0+j] -> a_s[j][i]  (transpose into smem)
#pragma unroll
        for (int t = 0; t < 8; t++) {
            int idx = tid + t * 128;
            int i = idx >> 5, j = idx & 31;
            a_s[j][i] = x[(n0 + i) * IN_CH + k0 + j];
        }
        // B: theta[k0+r][c] -> b_s[r][c]
#pragma unroll
        for (int t = 0; t < 4; t++) {
            int idx4 = tid + t * 128;
            int r = idx4 >> 4, c4 = idx4 & 15;
            ((float4*)b_s[r])[c4] = ((const float4*)(theta + (k0 + r) * OUT_CH))[c4];
        }
        __syncthreads();
#pragma unroll
        for (int k = 0; k < 32; k++) {
            float a0 = a_s[k][rg * 2 + 0];
            float a1 = a_s[k][rg * 2 + 1];
            float4 b0 = *(float4*)&b_s[k][cg * 8 + 0];
            float4 b1 = *(float4*)&b_s[k][cg * 8 + 4];
            float bb[8] = {b0.x, b0.y, b0.z, b0.w, b1.x, b1.y, b1.z, b1.w};
#pragma unroll
            for (int j = 0; j < 8; j++) {
                acc[0][j] += a0 * bb[j];
                acc[1][j] += a1 * bb[j];
            }
        }
        __syncthreads();
    }
#pragma unroll
    for (int i = 0; i < 2; i++) {
        int n = n0 + rg * 2 + i;
        float4 o0 = make_float4(acc[i][0], acc[i][1], acc[i][2], acc[i][3]);
        float4 o1 = make_float4(acc[i][4], acc[i][5], acc[i][6], acc[i][7]);
        *(float4*)&g_xw[n * OUT_CH + cg * 8 + 0] = o0;
        *(float4*)&g_xw[n * OUT_CH + cg * 8 + 4] = o1;
    }
}

// ---------------------------------------------------------------------------
// Kernel 2: g_ef[e][c] = (sum_n H[n][e] * g_xw[n][c]) / de[e],
//           de[e] = sum_n H[n][e]   (computed inline — block owns all n).
// Block: 128 threads, 32 e x 64 c tile, K-loop over all N. Grid: ceil(E/32).
// ---------------------------------------------------------------------------
__global__ __launch_bounds__(128) void k_edge(const float* __restrict__ H) {
    __shared__ float a_s[32][32];   // [k=n][e]  (H slab, already k-major)
    __shared__ float b_s[32][64];   // [k=n][c]  (xw slab)
    const int tid = threadIdx.x;
    const int eg  = tid >> 3;       // 0..15 -> 2 e's each
    const int cg  = tid & 7;        // 0..7  -> 8 c's each
    const int e0  = blockIdx.x * 32;

    float acc[2][8];
#pragma unroll
    for (int i = 0; i < 2; i++)
#pragma unroll
        for (int j = 0; j < 8; j++) acc[i][j] = 0.f;
    float de0 = 0.f, de1 = 0.f;

    for (int n0 = 0; n0 < N_NODES; n0 += 32) {
        // A: H[n0+i][e0+j] -> a_s[i][j]
#pragma unroll
        for (int t = 0; t < 8; t++) {
            int idx = tid + t * 128;
            int i = idx >> 5, j = idx & 31;
            int e = e0 + j;
            a_s[i][j] = (e < N_EDGES) ? H[(long)(n0 + i) * N_EDGES + e] : 0.f;
        }
        // B: g_xw[n0+r][c] -> b_s[r][c]
#pragma unroll
        for (int t = 0; t < 4; t++) {
            int idx4 = tid + t * 128;
            int r = idx4 >> 4, c4 = idx4 & 15;
            ((float4*)b_s[r])[c4] = ((const float4*)(g_xw + (n0 + r) * OUT_CH))[c4];
        }
        __syncthreads();
#pragma unroll
        for (int k = 0; k < 32; k++) {
            float a0 = a_s[k][eg * 2 + 0];
            float a1 = a_s[k][eg * 2 + 1];
            float4 b0 = *(float4*)&b_s[k][cg * 8 + 0];
            float4 b1 = *(float4*)&b_s[k][cg * 8 + 4];
            de0 += a0;
            de1 += a1;
            float bb[8] = {b0.x, b0.y, b0.z, b0.w, b1.x, b1.y, b1.z, b1.w};
#pragma unroll
            for (int j = 0; j < 8; j++) {
                acc[0][j] += a0 * bb[j];
                acc[1][j] += a1 * bb[j];
            }
        }
        __syncthreads();
    }
    float inv0 = 1.f / de0;
    float inv1 = 1.f / de1;
#pragma unroll
    for (int i = 0; i < 2; i++) {
        int e = e0 + eg * 2 + i;
        if (e < N_EDGES) {
            float inv = (i == 0) ? inv0 : inv1;
            float4 o0 = make_float4(acc[i][0] * inv, acc[i][1] * inv,
                                    acc[i][2] * inv, acc[i][3] * inv);
            float4 o1 = make_float4(acc[i][4] * inv, acc[i][5] * inv,
                                    acc[i][6] * inv, acc[i][7] * inv);
            *(float4*)&g_ef[e * OUT_CH + cg * 8 + 0] = o0;
            *(float4*)&g_ef[e * OUT_CH + cg * 8 + 4] = o1;
        }
    }
}

// ---------------------------------------------------------------------------
// Kernel 3: out[n][c] = (sum_e H[n][e] * g_ef[e][c]) / dn[n],
//           dn[n] = sum_e H[n][e]   (computed inline — block owns all e).
// Block: 128 threads, 32 n x 64 c tile, K-loop over all E. Grid: N/32 = 625.
// ---------------------------------------------------------------------------
__global__ __launch_bounds__(128) void k_node(const float* __restrict__ H,
                                              float* __restrict__ out) {
    __shared__ float a_s[32][33];   // [k=e][n]  transposed, padded
    __shared__ float b_s[32][64];   // [k=e][c]  edge-feature slab
    const int tid = threadIdx.x;
    const int ng  = tid >> 3;       // 0..15 -> 2 n's each
    const int cg  = tid & 7;        // 0..7  -> 8 c's each
    const int n0  = blockIdx.x * 32;

    float acc[2][8];
#pragma unroll
    for (int i = 0; i < 2; i++)
#pragma unroll
        for (int j = 0; j < 8; j++) acc[i][j] = 0.f;
    float dn0 = 0.f, dn1 = 0.f;

    for (int e0 = 0; e0 < N_EDGES; e0 += 32) {
        // A: H[n0+i][e0+j] -> a_s[j][i]  (transpose; pad kills STS conflicts)
#pragma unroll
        for (int t = 0; t < 8; t++) {
            int idx = tid + t * 128;
            int i = idx >> 5, j = idx & 31;
            int e = e0 + j;
            a_s[j][i] = (e < N_EDGES) ? H[(long)(n0 + i) * N_EDGES + e] : 0.f;
        }
        // B: g_ef[e0+r][c] -> b_s[r][c]
#pragma unroll
        for (int t = 0; t < 4; t++) {
            int idx4 = tid + t * 128;
            int r = idx4 >> 4, c4 = idx4 & 15;
            int e = e0 + r;
            float4 v = make_float4(0.f, 0.f, 0.f, 0.f);
            if (e < N_EDGES) v = ((const float4*)(g_ef + e * OUT_CH))[c4];
            ((float4*)b_s[r])[c4] = v;
        }
        __syncthreads();
#pragma unroll
        for (int k = 0; k < 32; k++) {
            float a0 = a_s[k][ng * 2 + 0];
            float a1 = a_s[k][ng * 2 + 1];
            float4 b0 = *(float4*)&b_s[k][cg * 8 + 0];
            float4 b1 = *(float4*)&b_s[k][cg * 8 + 4];
            dn0 += a0;
            dn1 += a1;
            float bb[8] = {b0.x, b0.y, b0.z, b0.w, b1.x, b1.y, b1.z, b1.w};
#pragma unroll
            for (int j = 0; j < 8; j++) {
                acc[0][j] += a0 * bb[j];
                acc[1][j] += a1 * bb[j];
            }
        }
        __syncthreads();
    }
    float inv0 = 1.f / dn0;
    float inv1 = 1.f / dn1;
#pragma unroll
    for (int i = 0; i < 2; i++) {
        int n = n0 + ng * 2 + i;
        float inv = (i == 0) ? inv0 : inv1;
        float4 o0 = make_float4(acc[i][0] * inv, acc[i][1] * inv,
                                acc[i][2] * inv, acc[i][3] * inv);
        float4 o1 = make_float4(acc[i][4] * inv, acc[i][5] * inv,
                                acc[i][6] * inv, acc[i][7] * inv);
        *(float4*)&out[n * OUT_CH + cg * 8 + 0] = o0;
        *(float4*)&out[n * OUT_CH + cg * 8 + 4] = o1;
    }
}

// ---------------------------------------------------------------------------
extern "C" void kernel_launch(void* const* d_in, const int* in_sizes, int n_in,
                              void* d_out, int out_size) {
    const float* x     = (const float*)d_in[0];   // [20000, 128]
    const float* H     = (const float*)d_in[1];   // [20000, 10000]
    const float* theta = (const float*)d_in[2];   // [128, 64]
    float* out         = (float*)d_out;           // [20000, 64]

    k_xw<<<N_NODES / 32, 128>>>(x, theta);
    k_edge<<<(N_EDGES + 31) / 32, 128>>>(H);
    k_node<<<N_NODES / 32, 128>>>(H, out);
    (void)in_sizes; (void)n_in; (void)out_size;
}

// round 5
// speedup vs baseline: 1.6113x; 1.6113x over previous
#include <cuda_runtime.h>

#define NN 20000
#define NE 10000
#define IC 128
#define OC 64

// Scratch (device globals — no allocation in kernel_launch).
__device__ float g_xwT_hi[OC * NN];   // tf32(xw)^T           [64][20000]
__device__ float g_xwT_lo[OC * NN];   // tf32(xw - hi)^T      [64][20000]
__device__ float g_ef[NE * OC];       // edge features        [E][64]

// ---------------------------------------------------------------------------
// helpers
// ---------------------------------------------------------------------------
__device__ __forceinline__ float to_tf32(float x) {
    unsigned u;
    asm("cvt.rna.tf32.f32 %0, %1;" : "=r"(u) : "f"(x));
    return __uint_as_float(u);
}
__device__ __forceinline__ float4 to_tf32_4(float4 v) {
    return make_float4(to_tf32(v.x), to_tf32(v.y), to_tf32(v.z), to_tf32(v.w));
}
// mma.m16n8k8 tf32: A row-major [16,8], B col-major [8,8], C fp32 [16,8]
// A frag: a0=(g,q) a1=(g+8,q) a2=(g,q+4) a3=(g+8,q+4)
// B frag: b0=(k=q,n=g) b1=(k=q+4,n=g)
// C frag: c0=(g,2q) c1=(g,2q+1) c2=(g+8,2q) c3=(g+8,2q+1)
__device__ __forceinline__ void mma8(float* c, unsigned a0, unsigned a1,
                                     unsigned a2, unsigned a3,
                                     unsigned b0, unsigned b1) {
    asm volatile(
        "mma.sync.aligned.m16n8k8.row.col.f32.tf32.tf32.f32 "
        "{%0,%1,%2,%3}, {%4,%5,%6,%7}, {%8,%9}, {%0,%1,%2,%3};\n"
        : "+f"(c[0]), "+f"(c[1]), "+f"(c[2]), "+f"(c[3])
        : "r"(a0), "r"(a1), "r"(a2), "r"(a3), "r"(b0), "r"(b1));
}
__device__ __forceinline__ unsigned ldsu(const float* p) {
    return __float_as_uint(*p);
}

// ---------------------------------------------------------------------------
// Kernel 1: xw = x @ theta, stored TRANSPOSED as tf32 hi/lo pairs.
// ---------------------------------------------------------------------------
__global__ __launch_bounds__(128) void k_xw(const float* __restrict__ x,
                                            const float* __restrict__ theta) {
    __shared__ float a_s[32][33];
    __shared__ float b_s[32][64];
    const int tid = threadIdx.x;
    const int rg  = tid >> 3;
    const int cg  = tid & 7;
    const int n0  = blockIdx.x * 32;

    float acc[2][8];
#pragma unroll
    for (int i = 0; i < 2; i++)
#pragma unroll
        for (int j = 0; j < 8; j++) acc[i][j] = 0.f;

    for (int k0 = 0; k0 < IC; k0 += 32) {
#pragma unroll
        for (int t = 0; t < 8; t++) {
            int idx = tid + t * 128;
            int i = idx >> 5, j = idx & 31;
            a_s[j][i] = x[(n0 + i) * IC + k0 + j];
        }
#pragma unroll
        for (int t = 0; t < 4; t++) {
            int idx4 = tid + t * 128;
            int r = idx4 >> 4, c4 = idx4 & 15;
            ((float4*)b_s[r])[c4] = ((const float4*)(theta + (k0 + r) * OC))[c4];
        }
        __syncthreads();
#pragma unroll
        for (int k = 0; k < 32; k++) {
            float a0 = a_s[k][rg * 2 + 0];
            float a1 = a_s[k][rg * 2 + 1];
            float4 b0 = *(float4*)&b_s[k][cg * 8 + 0];
            float4 b1 = *(float4*)&b_s[k][cg * 8 + 4];
            float bb[8] = {b0.x, b0.y, b0.z, b0.w, b1.x, b1.y, b1.z, b1.w};
#pragma unroll
            for (int j = 0; j < 8; j++) {
                acc[0][j] += a0 * bb[j];
                acc[1][j] += a1 * bb[j];
            }
        }
        __syncthreads();
    }
#pragma unroll
    for (int i = 0; i < 2; i++) {
        int n = n0 + rg * 2 + i;
#pragma unroll
        for (int j = 0; j < 8; j++) {
            int c = cg * 8 + j;
            float v  = acc[i][j];
            float hi = to_tf32(v);
            float lo = to_tf32(v - hi);
            g_xwT_hi[c * NN + n] = hi;
            g_xwT_lo[c * NN + n] = lo;
        }
    }
}

// ---------------------------------------------------------------------------
// Kernel 2 (pass 1, transposed form):
//   ef^T[c][e] = sum_n xwT[c][n] * H[n][e], then divide by de[e] = colsum(H).
//   A = xwT hi/lo (row-major [c][k]), B = H tile natural ([k=n][e]).
// Block: 128 thr / 4 warps. Tile: M(c)=64 x N(e)=64. BK=32. Grid: ceil(E/64).
// ---------------------------------------------------------------------------
__global__ __launch_bounds__(128) void k_edge_t(const float* __restrict__ H) {
    __shared__ float As_hi[64][36];
    __shared__ float As_lo[64][36];
    __shared__ float Bs[32][72];
    __shared__ float sde[128];
    __shared__ float sinv[64];

    const int tid  = threadIdx.x;
    const int lane = tid & 31;
    const int w    = tid >> 5;
    const int g    = lane >> 2;
    const int q    = lane & 3;
    const int e0   = blockIdx.x * 64;

    float acc[8][4];
#pragma unroll
    for (int nt = 0; nt < 8; nt++)
#pragma unroll
        for (int r = 0; r < 4; r++) acc[nt][r] = 0.f;
    float de_acc = 0.f;

    const int ac = tid >> 1;          // A row (channel) 0..63
    const int ak = (tid & 1) * 16;    // A k-half
    const int br = tid >> 2;          // B row (k) 0..31
    const int bc = (tid & 3) * 4;     // B col base

    for (int k0 = 0; k0 < NN; k0 += 32) {
        // A tiles (already tf32 hi/lo in global)
        {
            const float4* sh = (const float4*)(g_xwT_hi + ac * NN + k0 + ak);
            const float4* sl = (const float4*)(g_xwT_lo + ac * NN + k0 + ak);
            float4* dh = (float4*)&As_hi[ac][ak];
            float4* dl = (float4*)&As_lo[ac][ak];
#pragma unroll
            for (int u = 0; u < 4; u++) { dh[u] = sh[u]; dl[u] = sl[u]; }
        }
        // B tile: H[k0+br][e0 + bc + 16*it], tf32-convert, zero-fill OOB e
        {
            long rowoff = (long)(k0 + br) * NE;
#pragma unroll
            for (int it = 0; it < 4; it++) {
                int ec = bc + it * 16;
                int e  = e0 + ec;
                float4 v = (e < NE) ? *(const float4*)(H + rowoff + e)
                                    : make_float4(0.f, 0.f, 0.f, 0.f);
                *(float4*)&Bs[br][ec] = to_tf32_4(v);
            }
        }
        __syncthreads();
        // de partial: thread -> col (tid&63), k-half (tid>>6). Conflict-free.
        {
            int c = tid & 63, h = (tid >> 6) * 16;
#pragma unroll
            for (int k = 0; k < 16; k++) de_acc += Bs[h + k][c];
        }
        // mma
#pragma unroll
        for (int ks = 0; ks < 32; ks += 8) {
            const int cr = w * 16;
            unsigned ah0 = ldsu(&As_hi[cr + g][ks + q]);
            unsigned ah1 = ldsu(&As_hi[cr + g + 8][ks + q]);
            unsigned ah2 = ldsu(&As_hi[cr + g][ks + q + 4]);
            unsigned ah3 = ldsu(&As_hi[cr + g + 8][ks + q + 4]);
            unsigned al0 = ldsu(&As_lo[cr + g][ks + q]);
            unsigned al1 = ldsu(&As_lo[cr + g + 8][ks + q]);
            unsigned al2 = ldsu(&As_lo[cr + g][ks + q + 4]);
            unsigned al3 = ldsu(&As_lo[cr + g + 8][ks + q + 4]);
#pragma unroll
            for (int nt = 0; nt < 8; nt++) {
                unsigned b0 = ldsu(&Bs[ks + q][nt * 8 + g]);
                unsigned b1 = ldsu(&Bs[ks + q + 4][nt * 8 + g]);
                mma8(acc[nt], ah0, ah1, ah2, ah3, b0, b1);
                mma8(acc[nt], al0, al1, al2, al3, b0, b1);
            }
        }
        __syncthreads();
    }

    sde[tid] = de_acc;
    __syncthreads();
    if (tid < 64) sinv[tid] = 1.f / (sde[tid] + sde[tid + 64]);
    __syncthreads();

    // epilogue: out rows = channels c, cols = edges e (store transposed back)
    const int c0r = w * 16 + g;
    const int c1r = c0r + 8;
#pragma unroll
    for (int nt = 0; nt < 8; nt++) {
        int el0 = nt * 8 + 2 * q;
        int el1 = el0 + 1;
        float i0 = sinv[el0];
        float i1 = sinv[el1];
        int eA = e0 + el0, eB = e0 + el1;
        if (eA < NE) {
            g_ef[eA * OC + c0r] = acc[nt][0] * i0;
            g_ef[eA * OC + c1r] = acc[nt][2] * i0;
        }
        if (eB < NE) {
            g_ef[eB * OC + c0r] = acc[nt][1] * i1;
            g_ef[eB * OC + c1r] = acc[nt][3] * i1;
        }
    }
}

// ---------------------------------------------------------------------------
// Kernel 3 (pass 2, natural form):
//   out[n][c] = (sum_e H[n][e] * ef[e][c]) / dn[n], dn = rowsum(H) in fp32.
//   A = H rows (row-major [n][e]), B = ef natural ([k=e][c]).
// Block: 128 thr / 4 warps. Tile: M(n)=128 x N(c)=64. BK=32. Grid: ceil(N/128).
// ---------------------------------------------------------------------------
__global__ __launch_bounds__(128) void k_node2(const float* __restrict__ H,
                                               float* __restrict__ out) {
    __shared__ float As[128][36];
    __shared__ float Bs[32][72];
    __shared__ float sinv[128];

    const int tid  = threadIdx.x;
    const int lane = tid & 31;
    const int w    = tid >> 5;
    const int g    = lane >> 2;
    const int q    = lane & 3;
    const int n0   = blockIdx.x * 128;

    float acc[2][8][4];
#pragma unroll
    for (int s = 0; s < 2; s++)
#pragma unroll
        for (int nt = 0; nt < 8; nt++)
#pragma unroll
            for (int r = 0; r < 4; r++) acc[s][nt][r] = 0.f;
    float dn_acc = 0.f;

    const bool arow_ok = (n0 + tid) < NN;
    const long aoff    = (long)(n0 + tid) * NE;
    const int  br      = tid >> 2;
    const int  bc      = (tid & 3) * 4;

    for (int k0 = 0; k0 < NE; k0 += 32) {
        const int krem = NE - k0;   // 32, except last iter = 16
        // A: one full H row-strip per thread; accumulate fp32 dn for free
#pragma unroll
        for (int u = 0; u < 8; u++) {
            float4 v = make_float4(0.f, 0.f, 0.f, 0.f);
            if (arow_ok && (4 * u < krem)) v = *(const float4*)(H + aoff + k0 + 4 * u);
            dn_acc += (v.x + v.y) + (v.z + v.w);
            *(float4*)&As[tid][4 * u] = to_tf32_4(v);
        }
        // B: ef tile, tf32-convert, zero-fill OOB k
        {
            int e = k0 + br;
#pragma unroll
            for (int it = 0; it < 4; it++) {
                int c = bc + it * 16;
                float4 v = (e < NE) ? *(const float4*)(g_ef + e * OC + c)
                                    : make_float4(0.f, 0.f, 0.f, 0.f);
                *(float4*)&Bs[br][c] = to_tf32_4(v);
            }
        }
        __syncthreads();
#pragma unroll
        for (int ks = 0; ks < 32; ks += 8) {
            unsigned a[2][4];
#pragma unroll
            for (int s = 0; s < 2; s++) {
                int mr = w * 32 + s * 16;
                a[s][0] = ldsu(&As[mr + g][ks + q]);
                a[s][1] = ldsu(&As[mr + g + 8][ks + q]);
                a[s][2] = ldsu(&As[mr + g][ks + q + 4]);
                a[s][3] = ldsu(&As[mr + g + 8][ks + q + 4]);
            }
#pragma unroll
            for (int nt = 0; nt < 8; nt++) {
                unsigned b0 = ldsu(&Bs[ks + q][nt * 8 + g]);
                unsigned b1 = ldsu(&Bs[ks + q + 4][nt * 8 + g]);
                mma8(acc[0][nt], a[0][0], a[0][1], a[0][2], a[0][3], b0, b1);
                mma8(acc[1][nt], a[1][0], a[1][1], a[1][2], a[1][3], b0, b1);
            }
        }
        __syncthreads();
    }

    sinv[tid] = 1.f / dn_acc;   // row n0+tid (inf for OOB rows; stores guarded)
    __syncthreads();

#pragma unroll
    for (int s = 0; s < 2; s++) {
        int m0r = w * 32 + s * 16 + g;
        int m1r = m0r + 8;
        float iv0 = sinv[m0r];
        float iv1 = sinv[m1r];
        bool ok0 = (n0 + m0r) < NN;
        bool ok1 = (n0 + m1r) < NN;
#pragma unroll
        for (int nt = 0; nt < 8; nt++) {
            int col = nt * 8 + 2 * q;
            if (ok0) {
                float2 v = make_float2(acc[s][nt][0] * iv0, acc[s][nt][1] * iv0);
                *(float2*)&out[(n0 + m0r) * OC + col] = v;
            }
            if (ok1) {
                float2 v = make_float2(acc[s][nt][2] * iv1, acc[s][nt][3] * iv1);
                *(float2*)&out[(n0 + m1r) * OC + col] = v;
            }
        }
    }
}

// ---------------------------------------------------------------------------
extern "C" void kernel_launch(void* const* d_in, const int* in_sizes, int n_in,
                              void* d_out, int out_size) {
    const float* x     = (const float*)d_in[0];   // [20000, 128]
    const float* H     = (const float*)d_in[1];   // [20000, 10000]
    const float* theta = (const float*)d_in[2];   // [128, 64]
    float* out         = (float*)d_out;           // [20000, 64]

    k_xw<<<NN / 32, 128>>>(x, theta);
    k_edge_t<<<(NE + 63) / 64, 128>>>(H);
    k_node2<<<(NN + 127) / 128, 128>>>(H, out);
    (void)in_sizes; (void)n_in; (void)out_size;
}

// round 6
// speedup vs baseline: 5.8011x; 3.6003x over previous
#include <cuda_runtime.h>

#define NN 20000
#define NE 10000
#define IC 128
#define OC 64
#define SPLIT1 8
#define SPLIT2 4
#define CHUNK1 2528   // 79 k-tiles of 32
#define CHUNK2 2528

// Scratch (device globals — no allocation in kernel_launch).
__device__ float g_xwT_hi[OC * NN];          // tf32(xw)^T        [64][20000]
__device__ float g_xwT_lo[OC * NN];          // tf32(xw-hi)^T     [64][20000]
__device__ float g_ef[NE * OC];              // edge features     [E][64]
__device__ float g_ef_part[SPLIT1 * NE * OC];
__device__ float g_de_part[SPLIT1 * NE];
__device__ float g_out_part[SPLIT2 * NN * OC];
__device__ float g_dn_part[SPLIT2 * NN];

// ---------------------------------------------------------------------------
// helpers
// ---------------------------------------------------------------------------
__device__ __forceinline__ float to_tf32(float x) {
    unsigned u;
    asm("cvt.rna.tf32.f32 %0, %1;" : "=r"(u) : "f"(x));
    return __uint_as_float(u);
}
__device__ __forceinline__ unsigned tf32u(float x) {
    unsigned u;
    asm("cvt.rna.tf32.f32 %0, %1;" : "=r"(u) : "f"(x));
    return u;
}
// mma.m16n8k8 tf32: A row-major [16,8], B col-major [8,8], C fp32 [16,8]
__device__ __forceinline__ void mma8(float* c, unsigned a0, unsigned a1,
                                     unsigned a2, unsigned a3,
                                     unsigned b0, unsigned b1) {
    asm volatile(
        "mma.sync.aligned.m16n8k8.row.col.f32.tf32.tf32.f32 "
        "{%0,%1,%2,%3}, {%4,%5,%6,%7}, {%8,%9}, {%0,%1,%2,%3};\n"
        : "+f"(c[0]), "+f"(c[1]), "+f"(c[2]), "+f"(c[3])
        : "r"(a0), "r"(a1), "r"(a2), "r"(a3), "r"(b0), "r"(b1));
}
// cp.async 16B with zero-fill predicate (src-size 0 reads nothing)
__device__ __forceinline__ void cpa16(float* dst, const float* src, bool pred) {
    unsigned sdst = (unsigned)__cvta_generic_to_shared(dst);
    int sz = pred ? 16 : 0;
    asm volatile("cp.async.cg.shared.global [%0], [%1], 16, %2;\n"
                 :: "r"(sdst), "l"(src), "r"(sz));
}
__device__ __forceinline__ void cpa_commit() {
    asm volatile("cp.async.commit_group;\n");
}
template <int N>
__device__ __forceinline__ void cpa_wait() {
    asm volatile("cp.async.wait_group %0;\n" :: "n"(N));
}

// ---------------------------------------------------------------------------
// Kernel 1: xw = x @ theta, stored TRANSPOSED as tf32 hi/lo pairs.
// ---------------------------------------------------------------------------
__global__ __launch_bounds__(128) void k_xw(const float* __restrict__ x,
                                            const float* __restrict__ theta) {
    __shared__ float a_s[32][33];
    __shared__ float b_s[32][64];
    const int tid = threadIdx.x;
    const int rg  = tid >> 3;
    const int cg  = tid & 7;
    const int n0  = blockIdx.x * 32;

    float acc[2][8];
#pragma unroll
    for (int i = 0; i < 2; i++)
#pragma unroll
        for (int j = 0; j < 8; j++) acc[i][j] = 0.f;

    for (int k0 = 0; k0 < IC; k0 += 32) {
#pragma unroll
        for (int t = 0; t < 8; t++) {
            int idx = tid + t * 128;
            int i = idx >> 5, j = idx & 31;
            a_s[j][i] = x[(n0 + i) * IC + k0 + j];
        }
#pragma unroll
        for (int t = 0; t < 4; t++) {
            int idx4 = tid + t * 128;
            int r = idx4 >> 4, c4 = idx4 & 15;
            ((float4*)b_s[r])[c4] = ((const float4*)(theta + (k0 + r) * OC))[c4];
        }
        __syncthreads();
#pragma unroll
        for (int k = 0; k < 32; k++) {
            float a0 = a_s[k][rg * 2 + 0];
            float a1 = a_s[k][rg * 2 + 1];
            float4 b0 = *(float4*)&b_s[k][cg * 8 + 0];
            float4 b1 = *(float4*)&b_s[k][cg * 8 + 4];
            float bb[8] = {b0.x, b0.y, b0.z, b0.w, b1.x, b1.y, b1.z, b1.w};
#pragma unroll
            for (int j = 0; j < 8; j++) {
                acc[0][j] += a0 * bb[j];
                acc[1][j] += a1 * bb[j];
            }
        }
        __syncthreads();
    }
#pragma unroll
    for (int i = 0; i < 2; i++) {
        int n = n0 + rg * 2 + i;
#pragma unroll
        for (int j = 0; j < 8; j++) {
            int c = cg * 8 + j;
            float v  = acc[i][j];
            float hi = to_tf32(v);
            float lo = to_tf32(v - hi);
            g_xwT_hi[c * NN + n] = hi;
            g_xwT_lo[c * NN + n] = lo;
        }
    }
}

// ---------------------------------------------------------------------------
// Pass 1 (partial): ef^T[c][e] += sum_{n in chunk} xwT[c][n] * H[n][e]
// Tile M(c)=64 x N(e)=128, BK=32. 256 thr / 8 warps (4 M x 2 N).
// Grid (79, SPLIT1). Double-buffered cp.async. Raw H in smem (exact de);
// tf32 rounding applied at fragment-load time.
// ---------------------------------------------------------------------------
__global__ __launch_bounds__(256) void k_edge_p(const float* __restrict__ H) {
    extern __shared__ float sm[];
    float* Ah = sm;                   // [2][64*36]
    float* Al = sm + 2 * 2304;        // [2][64*36]
    float* Bs = sm + 4 * 2304;        // [2][32*136]
    __shared__ float sred[256];

    const int tid  = threadIdx.x;
    const int lane = tid & 31, w = tid >> 5;
    const int g = lane >> 2, q = lane & 3;
    const int wm = w & 3, wn = w >> 2;
    const int e0 = blockIdx.x * 128;
    const int sp = blockIdx.y;
    const int kbeg = sp * CHUNK1;
    const int kend = (kbeg + CHUNK1 < NN) ? (kbeg + CHUNK1) : NN;

    const int arow = tid >> 3;        // 0..31 (+32)
    const int ak4  = (tid & 7) * 4;
    const int brow = tid >> 3;        // 0..31
    const int bc0  = (tid & 7) * 4;

    float acc[8][4];
#pragma unroll
    for (int nt = 0; nt < 8; nt++)
#pragma unroll
        for (int r = 0; r < 4; r++) acc[nt][r] = 0.f;
    float de_acc = 0.f;

    auto load = [&](int buf, int k0) {
#pragma unroll
        for (int i = 0; i < 2; i++) {
            int r = arow + 32 * i;
            long go = (long)r * NN + k0 + ak4;
            cpa16(Ah + buf * 2304 + r * 36 + ak4, g_xwT_hi + go, true);
            cpa16(Al + buf * 2304 + r * 36 + ak4, g_xwT_lo + go, true);
        }
        long ho = (long)(k0 + brow) * NE;
#pragma unroll
        for (int j = 0; j < 4; j++) {
            int ec = bc0 + 32 * j;
            cpa16(Bs + buf * 4352 + brow * 136 + ec, H + ho + e0 + ec,
                  (e0 + ec) < NE);
        }
    };

    load(0, kbeg);
    cpa_commit();
    int buf = 0;
    for (int k0 = kbeg; k0 < kend; k0 += 32) {
        bool hn = (k0 + 32) < kend;
        if (hn) { load(buf ^ 1, k0 + 32); cpa_commit(); cpa_wait<1>(); }
        else    { cpa_wait<0>(); }
        __syncthreads();
        const float* ah = Ah + buf * 2304;
        const float* al = Al + buf * 2304;
        const float* bs = Bs + buf * 4352;
        {   // exact fp32 column-sum partial from raw H
            int col = tid >> 1, h = (tid & 1) * 16;
#pragma unroll
            for (int k = 0; k < 16; k++) de_acc += bs[(h + k) * 136 + col];
        }
#pragma unroll
        for (int ks = 0; ks < 32; ks += 8) {
            const int ar = wm * 16;
            unsigned h0 = __float_as_uint(ah[(ar + g) * 36 + ks + q]);
            unsigned h1 = __float_as_uint(ah[(ar + g + 8) * 36 + ks + q]);
            unsigned h2 = __float_as_uint(ah[(ar + g) * 36 + ks + q + 4]);
            unsigned h3 = __float_as_uint(ah[(ar + g + 8) * 36 + ks + q + 4]);
            unsigned l0 = __float_as_uint(al[(ar + g) * 36 + ks + q]);
            unsigned l1 = __float_as_uint(al[(ar + g + 8) * 36 + ks + q]);
            unsigned l2 = __float_as_uint(al[(ar + g) * 36 + ks + q + 4]);
            unsigned l3 = __float_as_uint(al[(ar + g + 8) * 36 + ks + q + 4]);
#pragma unroll
            for (int nt = 0; nt < 8; nt++) {
                unsigned b0 = tf32u(bs[(ks + q) * 136 + wn * 64 + nt * 8 + g]);
                unsigned b1 = tf32u(bs[(ks + q + 4) * 136 + wn * 64 + nt * 8 + g]);
                mma8(acc[nt], h0, h1, h2, h3, b0, b1);
                mma8(acc[nt], l0, l1, l2, l3, b0, b1);
            }
        }
        __syncthreads();
        buf ^= 1;
    }

    sred[tid] = de_acc;
    __syncthreads();
    if (tid < 128) {
        int e = e0 + tid;
        if (e < NE) g_de_part[sp * NE + e] = sred[2 * tid] + sred[2 * tid + 1];
    }

    float* op = g_ef_part + sp * NE * OC;
    const int c0 = wm * 16 + g;
#pragma unroll
    for (int nt = 0; nt < 8; nt++) {
        int eA = e0 + wn * 64 + nt * 8 + 2 * q;
        int eB = eA + 1;
        if (eA < NE) { op[eA * OC + c0] = acc[nt][0]; op[eA * OC + c0 + 8] = acc[nt][2]; }
        if (eB < NE) { op[eB * OC + c0] = acc[nt][1]; op[eB * OC + c0 + 8] = acc[nt][3]; }
    }
}

// Finalize pass 1: ef = (sum_s part) / (sum_s de_part)
__global__ __launch_bounds__(256) void k_fin1() {
    int idx = blockIdx.x * 256 + threadIdx.x;   // e*64 + c, exact cover
    int e = idx >> 6;
    float s = 0.f, d = 0.f;
#pragma unroll
    for (int sp = 0; sp < SPLIT1; sp++) {
        s += g_ef_part[sp * NE * OC + idx];
        d += g_de_part[sp * NE + e];
    }
    g_ef[idx] = s / d;
}

// ---------------------------------------------------------------------------
// Pass 2 (partial): out[n][c] += sum_{e in chunk} H[n][e] * ef[e][c]
// Tile M(n)=128 x N(c)=64, BK=32. 256 thr / 8 warps (4 M x 2 N).
// Grid (157, SPLIT2). Double-buffered cp.async; dn exact from raw H.
// ---------------------------------------------------------------------------
__global__ __launch_bounds__(256) void k_node_p(const float* __restrict__ H) {
    extern __shared__ float sm[];
    float* As = sm;                   // [2][128*36]
    float* Bs = sm + 2 * 4608;        // [2][32*72]
    __shared__ float sred[256];

    const int tid  = threadIdx.x;
    const int lane = tid & 31, w = tid >> 5;
    const int g = lane >> 2, q = lane & 3;
    const int wm = w & 3, wn = w >> 2;
    const int n0 = blockIdx.x * 128;
    const int sp = blockIdx.y;
    const int kbeg = sp * CHUNK2;
    const int kend = (kbeg + CHUNK2 < NE) ? (kbeg + CHUNK2) : NE;

    const int  arow   = tid >> 1;                 // 0..127
    const bool row_ok = (n0 + arow) < NN;
    const long aoff   = (long)(n0 + arow) * NE;
    const int  akb    = (tid & 1) * 16;
    const int  brow   = tid >> 3;                 // 0..31
    const int  bc0    = (tid & 7) * 4;

    float acc[2][4][4];
#pragma unroll
    for (int s2 = 0; s2 < 2; s2++)
#pragma unroll
        for (int nt = 0; nt < 4; nt++)
#pragma unroll
            for (int r = 0; r < 4; r++) acc[s2][nt][r] = 0.f;
    float dn_acc = 0.f;

    auto load = [&](int buf, int k0) {
#pragma unroll
        for (int j = 0; j < 4; j++) {
            int kf = akb + 4 * j;
            cpa16(As + buf * 4608 + arow * 36 + kf, H + aoff + k0 + kf,
                  row_ok && (k0 + kf + 4 <= NE));
        }
        int e = k0 + brow;
        bool eok = e < NE;
#pragma unroll
        for (int j = 0; j < 2; j++) {
            int cf = bc0 + 32 * j;
            cpa16(Bs + buf * 2304 + brow * 72 + cf, g_ef + e * OC + cf, eok);
        }
    };

    load(0, kbeg);
    cpa_commit();
    int buf = 0;
    for (int k0 = kbeg; k0 < kend; k0 += 32) {
        bool hn = (k0 + 32) < kend;
        if (hn) { load(buf ^ 1, k0 + 32); cpa_commit(); cpa_wait<1>(); }
        else    { cpa_wait<0>(); }
        __syncthreads();
        const float* as = As + buf * 4608;
        const float* bs = Bs + buf * 2304;
        {   // exact fp32 row-sum partial from raw H (zero-fills add 0)
            int r = tid >> 1, h = (tid & 1) * 16;
#pragma unroll
            for (int k = 0; k < 16; k++) dn_acc += as[r * 36 + h + k];
        }
#pragma unroll
        for (int ks = 0; ks < 32; ks += 8) {
            unsigned a[2][4];
#pragma unroll
            for (int s2 = 0; s2 < 2; s2++) {
                int m = wm * 32 + s2 * 16;
                a[s2][0] = tf32u(as[(m + g) * 36 + ks + q]);
                a[s2][1] = tf32u(as[(m + g + 8) * 36 + ks + q]);
                a[s2][2] = tf32u(as[(m + g) * 36 + ks + q + 4]);
                a[s2][3] = tf32u(as[(m + g + 8) * 36 + ks + q + 4]);
            }
#pragma unroll
            for (int nt = 0; nt < 4; nt++) {
                unsigned b0 = tf32u(bs[(ks + q) * 72 + wn * 32 + nt * 8 + g]);
                unsigned b1 = tf32u(bs[(ks + q + 4) * 72 + wn * 32 + nt * 8 + g]);
                mma8(acc[0][nt], a[0][0], a[0][1], a[0][2], a[0][3], b0, b1);
                mma8(acc[1][nt], a[1][0], a[1][1], a[1][2], a[1][3], b0, b1);
            }
        }
        __syncthreads();
        buf ^= 1;
    }

    sred[tid] = dn_acc;
    __syncthreads();
    if (tid < 128) {
        int n = n0 + tid;
        if (n < NN) g_dn_part[sp * NN + n] = sred[2 * tid] + sred[2 * tid + 1];
    }

    float* op = g_out_part + sp * NN * OC;
#pragma unroll
    for (int s2 = 0; s2 < 2; s2++) {
        int nA = n0 + wm * 32 + s2 * 16 + g;
        int nB = nA + 8;
#pragma unroll
        for (int nt = 0; nt < 4; nt++) {
            int c = wn * 32 + nt * 8 + 2 * q;
            if (nA < NN)
                *(float2*)&op[nA * OC + c] = make_float2(acc[s2][nt][0], acc[s2][nt][1]);
            if (nB < NN)
                *(float2*)&op[nB * OC + c] = make_float2(acc[s2][nt][2], acc[s2][nt][3]);
        }
    }
}

// Finalize pass 2: out = (sum_s part) / (sum_s dn_part)
__global__ __launch_bounds__(256) void k_fin2(float* __restrict__ out) {
    int idx = blockIdx.x * 256 + threadIdx.x;   // n*64 + c, exact cover
    int n = idx >> 6;
    float s = 0.f, d = 0.f;
#pragma unroll
    for (int sp = 0; sp < SPLIT2; sp++) {
        s += g_out_part[sp * NN * OC + idx];
        d += g_dn_part[sp * NN + n];
    }
    out[idx] = s / d;
}

// ---------------------------------------------------------------------------
extern "C" void kernel_launch(void* const* d_in, const int* in_sizes, int n_in,
                              void* d_out, int out_size) {
    const float* x     = (const float*)d_in[0];   // [20000, 128]
    const float* H     = (const float*)d_in[1];   // [20000, 10000]
    const float* theta = (const float*)d_in[2];   // [128, 64]
    float* out         = (float*)d_out;           // [20000, 64]

    cudaFuncSetAttribute(k_edge_p, cudaFuncAttributeMaxDynamicSharedMemorySize, 71680);
    cudaFuncSetAttribute(k_node_p, cudaFuncAttributeMaxDynamicSharedMemorySize, 55296);

    k_xw<<<NN / 32, 128>>>(x, theta);
    k_edge_p<<<dim3(79, SPLIT1), 256, 71680>>>(H);
    k_fin1<<<(NE * OC) / 256, 256>>>();
    k_node_p<<<dim3(157, SPLIT2), 256, 55296>>>(H);
    k_fin2<<<(NN * OC) / 256, 256>>>(out);
    (void)in_sizes; (void)n_in; (void)out_size;
}